// round 2
// baseline (speedup 1.0000x reference)
#include <cuda_runtime.h>
#include <cuda_bf16.h>
#include <math.h>

#define NN 20000
#define TT 256
#define EE 320000
#define GG 64
#define CTC 8
#define CPC 16
#define EMB 768
#define NOUT 4
#define FIN 512
#define BN_EPS 1e-5f

// ---------------- scratch (device globals: allocation-free) ----------------
__device__ float g_h0[(size_t)NN * FIN];     // pooled conv features
__device__ float g_agg[(size_t)NN * EMB];    // edge aggregation buffer
__device__ float g_z[(size_t)NN * EMB];      // GIN hidden
__device__ float g_h1[(size_t)NN * EMB];     // GIN1 output
__device__ float g_h2[(size_t)NN * EMB];     // GIN2 output
__device__ float g_pool[(size_t)GG * EMB];   // per-graph sums
__device__ float g_cnt[GG];                  // per-graph counts

// ---------------- fused temporal conv stack ----------------
// grid = NN blocks, 256 threads (one per time step)
__global__ void conv_kernel(const float* __restrict__ x,
                            const float* __restrict__ w0,
                            const float* __restrict__ bn0g, const float* __restrict__ bn0b,
                            const float* __restrict__ bn0m, const float* __restrict__ bn0v,
                            const float* __restrict__ w1,
                            const float* __restrict__ w2,
                            const float* __restrict__ bn2g, const float* __restrict__ bn2b,
                            const float* __restrict__ bn2m, const float* __restrict__ bn2v,
                            float* __restrict__ h0out)
{
    __shared__ float sx[TT];
    __shared__ float s1[TT][CTC + 1];   // padded: stride 9, conflict-free
    __shared__ float s2[TT][CPC + 1];   // padded: stride 17
    __shared__ float sw0[33 * CTC];
    __shared__ float sw1[21 * CTC];
    __shared__ float sw2[CTC * CPC];
    __shared__ float sb0s[CTC], sb0b[CTC], sb2s[CPC], sb2b[CPC];

    const int n = blockIdx.x;
    const int t = threadIdx.x;

    for (int i = t; i < 33 * CTC; i += 256) sw0[i] = w0[i];
    for (int i = t; i < 21 * CTC; i += 256) sw1[i] = w1[i];
    for (int i = t; i < CTC * CPC; i += 256) sw2[i] = w2[i];
    if (t < CTC) {
        float s = bn0g[t] * rsqrtf(bn0v[t] + BN_EPS);
        sb0s[t] = s;
        sb0b[t] = bn0b[t] - bn0m[t] * s;
    }
    if (t < CPC) {
        float s = bn2g[t] * rsqrtf(bn2v[t] + BN_EPS);
        sb2s[t] = s;
        sb2b[t] = bn2b[t] - bn2m[t] * s;
    }
    sx[t] = x[(size_t)n * TT + t];
    __syncthreads();

    // conv0: k=33, pad 16, 1->8 channels, then bn0
    float c0[CTC];
#pragma unroll
    for (int c = 0; c < CTC; c++) c0[c] = 0.f;
#pragma unroll 1
    for (int j = 0; j < 33; j++) {
        int tt = t + j - 16;
        float v = (tt >= 0 && tt < TT) ? sx[tt] : 0.f;
#pragma unroll
        for (int c = 0; c < CTC; c++) c0[c] += v * sw0[j * CTC + c];
    }
#pragma unroll
    for (int c = 0; c < CTC; c++) s1[t][c] = c0[c] * sb0s[c] + sb0b[c];
    __syncthreads();

    // depthwise conv: k=21, pad 10, then relu
    float d[CTC];
#pragma unroll
    for (int c = 0; c < CTC; c++) d[c] = 0.f;
#pragma unroll 1
    for (int j = 0; j < 21; j++) {
        int tt = t + j - 10;
        if (tt >= 0 && tt < TT) {
#pragma unroll
            for (int c = 0; c < CTC; c++) d[c] += s1[tt][c] * sw1[j * CTC + c];
        }
    }
#pragma unroll
    for (int c = 0; c < CTC; c++) d[c] = fmaxf(d[c], 0.f);

    // 1x1 conv 8->16, bn2, relu
#pragma unroll
    for (int o = 0; o < CPC; o++) {
        float a = 0.f;
#pragma unroll
        for (int c = 0; c < CTC; c++) a += d[c] * sw2[c * CPC + o];
        a = a * sb2s[o] + sb2b[o];
        s2[t][o] = fmaxf(a, 0.f);
    }
    __syncthreads();

    // mean pool over 8 time steps -> (32, 16) -> flat 512
    for (int idx = t; idx < 32 * CPC; idx += 256) {
        int tp = idx / CPC, o = idx % CPC;
        float s = 0.f;
#pragma unroll
        for (int p = 0; p < 8; p++) s += s2[tp * 8 + p][o];
        h0out[(size_t)n * FIN + tp * CPC + o] = s * 0.125f;
    }
}

// ---------------- utility: zero a buffer ----------------
__global__ void zero_kernel(float* __restrict__ p, int n) {
    int i = blockIdx.x * blockDim.x + threadIdx.x;
    if (i < n) p[i] = 0.f;
}

// ---------------- edge aggregation: agg[dst] += h[src] ----------------
// F/4 consecutive threads per edge -> coalesced float4 reads + coalesced atomics
__global__ void agg_kernel(const float* __restrict__ h,
                           const int* __restrict__ src,
                           const int* __restrict__ dst,
                           float* __restrict__ agg, int F)
{
    int per = F >> 2;
    int tid = blockIdx.x * blockDim.x + threadIdx.x;
    int e = tid / per;
    if (e >= EE) return;
    int f4 = tid - e * per;
    int s = src[e];
    int d0 = dst[e];
    float4 v = *(const float4*)(h + (size_t)s * F + f4 * 4);
    float* a = agg + (size_t)d0 * F + f4 * 4;
    atomicAdd(a + 0, v.x);
    atomicAdd(a + 1, v.y);
    atomicAdd(a + 2, v.z);
    atomicAdd(a + 3, v.w);
}

// ---------------- SGEMM: C = act((A [+ Aadd]) @ B + bias) ----------------
// BM=128, BN=64, BK=16, 256 threads, 8x4 micro-tile. K % 16 == 0, Nc % 64 == 0.
__global__ __launch_bounds__(256) void gemm_kernel(
    const float* __restrict__ A, const float* __restrict__ Aadd,
    const float* __restrict__ B, const float* __restrict__ bias,
    float* __restrict__ C, int M, int K, int Nc, int doRelu)
{
    __shared__ float As[16][129];  // [k][m], padded
    __shared__ float Bs[16][64];   // [k][n]

    const int tid = threadIdx.x;
    const int m0 = blockIdx.y * 128;
    const int n0 = blockIdx.x * 64;
    const int ty = tid >> 4;       // 0..15, 8 rows each
    const int tx = tid & 15;       // 0..15, 4 cols each

    const int arow = tid >> 2;     // 0..63
    const int aquad = tid & 3;     // 0..3 (float4 within a 16-wide k slice)
    const int brow = tid >> 4;     // 0..15
    const int bcol = (tid & 15) << 2;

    float acc[8][4];
#pragma unroll
    for (int i = 0; i < 8; i++)
#pragma unroll
        for (int j = 0; j < 4; j++) acc[i][j] = 0.f;

    for (int k0 = 0; k0 < K; k0 += 16) {
#pragma unroll
        for (int h = 0; h < 2; h++) {
            int m = m0 + arow + h * 64;
            float4 v = make_float4(0.f, 0.f, 0.f, 0.f);
            if (m < M) {
                v = *(const float4*)(A + (size_t)m * K + k0 + aquad * 4);
                if (Aadd) {
                    float4 w = *(const float4*)(Aadd + (size_t)m * K + k0 + aquad * 4);
                    v.x += w.x; v.y += w.y; v.z += w.z; v.w += w.w;
                }
            }
            As[aquad * 4 + 0][arow + h * 64] = v.x;
            As[aquad * 4 + 1][arow + h * 64] = v.y;
            As[aquad * 4 + 2][arow + h * 64] = v.z;
            As[aquad * 4 + 3][arow + h * 64] = v.w;
        }
        *(float4*)&Bs[brow][bcol] = *(const float4*)(B + (size_t)(k0 + brow) * Nc + n0 + bcol);
        __syncthreads();

#pragma unroll
        for (int k = 0; k < 16; k++) {
            float a[8], b[4];
#pragma unroll
            for (int i = 0; i < 8; i++) a[i] = As[k][ty * 8 + i];
#pragma unroll
            for (int j = 0; j < 4; j++) b[j] = Bs[k][tx * 4 + j];
#pragma unroll
            for (int i = 0; i < 8; i++)
#pragma unroll
                for (int j = 0; j < 4; j++) acc[i][j] += a[i] * b[j];
        }
        __syncthreads();
    }

#pragma unroll
    for (int i = 0; i < 8; i++) {
        int m = m0 + ty * 8 + i;
        if (m >= M) continue;
#pragma unroll
        for (int j = 0; j < 4; j++) {
            int n = n0 + tx * 4 + j;
            float c = acc[i][j] + bias[n];
            if (doRelu) c = fmaxf(c, 0.f);
            C[(size_t)m * Nc + n] = c;
        }
    }
}

// ---------------- graph mean-pool accumulation ----------------
__global__ void pool_kernel(const float* __restrict__ h,
                            const int* __restrict__ batch,
                            float* __restrict__ pool, float* __restrict__ cnt)
{
    int n = blockIdx.x;
    int b = batch[n];
    for (int f = threadIdx.x; f < EMB; f += blockDim.x)
        atomicAdd(&pool[(size_t)b * EMB + f], h[(size_t)n * EMB + f]);
    if (threadIdx.x == 0) atomicAdd(&cnt[b], 1.f);
}

// ---------------- final dense + log_softmax ----------------
__global__ void final_kernel(const float* __restrict__ dw,
                             const float* __restrict__ db,
                             const float* __restrict__ pool,
                             const float* __restrict__ cnt,
                             float* __restrict__ out)
{
    int g = threadIdx.x;
    if (g >= GG) return;
    float c = fmaxf(cnt[g], 1.f);
    float inv = 1.f / c;
    float acc[NOUT];
#pragma unroll
    for (int o = 0; o < NOUT; o++) acc[o] = db[o];
    for (int k = 0; k < EMB; k++) {
        float p = pool[(size_t)g * EMB + k] * inv;
#pragma unroll
        for (int o = 0; o < NOUT; o++) acc[o] += p * dw[k * NOUT + o];
    }
    float m = acc[0];
#pragma unroll
    for (int o = 1; o < NOUT; o++) m = fmaxf(m, acc[o]);
    float s = 0.f;
#pragma unroll
    for (int o = 0; o < NOUT; o++) s += expf(acc[o] - m);
    float lse = m + logf(s);
#pragma unroll
    for (int o = 0; o < NOUT; o++) out[g * NOUT + o] = acc[o] - lse;
}

// ---------------- launch ----------------
extern "C" void kernel_launch(void* const* d_in, const int* in_sizes, int n_in,
                              void* d_out, int out_size)
{
    const float* x       = (const float*)d_in[0];
    const int*   ei      = (const int*)d_in[1];
    const int*   batch   = (const int*)d_in[2];
    const float* conv0_w = (const float*)d_in[3];
    const float* bn0g    = (const float*)d_in[4];
    const float* bn0b    = (const float*)d_in[5];
    const float* bn0m    = (const float*)d_in[6];
    const float* bn0v    = (const float*)d_in[7];
    const float* conv1_w = (const float*)d_in[8];
    const float* conv2_w = (const float*)d_in[9];
    const float* bn2g    = (const float*)d_in[10];
    const float* bn2b    = (const float*)d_in[11];
    const float* bn2m    = (const float*)d_in[12];
    const float* bn2v    = (const float*)d_in[13];
    const float* gin1_w1 = (const float*)d_in[14];
    const float* gin1_b1 = (const float*)d_in[15];
    const float* gin1_w2 = (const float*)d_in[16];
    const float* gin1_b2 = (const float*)d_in[17];
    const float* gin2_w1 = (const float*)d_in[18];
    const float* gin2_b1 = (const float*)d_in[19];
    const float* gin2_w2 = (const float*)d_in[20];
    const float* gin2_b2 = (const float*)d_in[21];
    const float* dense_w = (const float*)d_in[22];
    const float* dense_b = (const float*)d_in[23];
    float* out = (float*)d_out;

    float *h0, *agg, *z, *h1, *h2, *pool, *cnt;
    cudaGetSymbolAddress((void**)&h0,   g_h0);
    cudaGetSymbolAddress((void**)&agg,  g_agg);
    cudaGetSymbolAddress((void**)&z,    g_z);
    cudaGetSymbolAddress((void**)&h1,   g_h1);
    cudaGetSymbolAddress((void**)&h2,   g_h2);
    cudaGetSymbolAddress((void**)&pool, g_pool);
    cudaGetSymbolAddress((void**)&cnt,  g_cnt);

    const int* src = ei;
    const int* dst = ei + EE;

    // 1. fused temporal conv stack -> h0 (N, 512)
    conv_kernel<<<NN, 256>>>(x, conv0_w, bn0g, bn0b, bn0m, bn0v,
                             conv1_w, conv2_w, bn2g, bn2b, bn2m, bn2v, h0);

    dim3 ggrid(EMB / 64, (NN + 127) / 128);

    // 2. GIN layer 1
    zero_kernel<<<(NN * FIN + 255) / 256, 256>>>(agg, NN * FIN);
    {
        int threads_total = EE * (FIN / 4);
        agg_kernel<<<(threads_total + 255) / 256, 256>>>(h0, src, dst, agg, FIN);
    }
    gemm_kernel<<<ggrid, 256>>>(h0, agg, gin1_w1, gin1_b1, z, NN, FIN, EMB, 1);
    gemm_kernel<<<ggrid, 256>>>(z, nullptr, gin1_w2, gin1_b2, h1, NN, EMB, EMB, 1);

    // 3. GIN layer 2
    zero_kernel<<<(NN * EMB + 255) / 256, 256>>>(agg, NN * EMB);
    {
        int threads_total = EE * (EMB / 4);
        agg_kernel<<<(threads_total + 255) / 256, 256>>>(h1, src, dst, agg, EMB);
    }
    gemm_kernel<<<ggrid, 256>>>(h1, agg, gin2_w1, gin2_b1, z, NN, EMB, EMB, 1);
    gemm_kernel<<<ggrid, 256>>>(z, nullptr, gin2_w2, gin2_b2, h2, NN, EMB, EMB, 1);

    // 4. per-graph mean pool + dense + log_softmax
    zero_kernel<<<(GG * EMB + 255) / 256, 256>>>(pool, GG * EMB);
    zero_kernel<<<1, GG>>>(cnt, GG);
    pool_kernel<<<NN, 256>>>(h2, batch, pool, cnt);
    final_kernel<<<1, 64>>>(dense_w, dense_b, pool, cnt, out);
}